// round 13
// baseline (speedup 1.0000x reference)
#include <cuda_runtime.h>

// QNNClassifier: 14-qubit statevector, BATCH=2048, DEPTH=8.
// One CTA/batch element; state = QDIM packed (re,im) u64 in smem (128 KB).
// CX deferred as GF(2) relabeling; per layer gates grouped 5+5+4 (same sigma
// frame => W=I; whole-layer diagonal applied once in pass 1; passes 2/3 pure
// real-shear). Coset addressing uses PRECOMPUTED parallel offsets Off[g]
// (XOR tree of the 4 walk masks) so all 32 LDS/STS per pass are independent
// (no serial Gray address chain). Pass 3 = spare-partner dual block; the
// final |amp|^2 reduction is fused into layer-8 pass-3. RY = 3-shear packed
// f32x2 butterflies, roles folded into constant sign bits. Bank-conflict-free.

#define NQ       14
#define QDIM     16384
#define DEPTH    8
#define NGATES   (DEPTH * NQ)   // 112
#define NPASSES  (DEPTH * 3)    // 24
#define NTHREADS 512

typedef unsigned long long u64;
typedef unsigned int u32;

struct __align__(16) Consts {
    int    piv[NPASSES][5];     // sorted pivot bits (pad 30)
    int    M[NPASSES][5];       // flip masks per gate
    int    F[NPASSES][5];       // parity masks per gate
    float  tq[NPASSES][5];      // tan(ty/4)
    float  sy[NPASSES][5];      // sin(ty/2)
    float  czH[NPASSES][5];     // cos(tz/2)
    float  szH[NPASSES][5];     // sin(tz/2)
    float  czF[NPASSES][5];     // cos(tz)
    float  szF[NPASSES][5];     // sin(tz)
    float2 T1[DEPTH][32];       // gates 5-9 half-angle products per 5-bit parity
    float2 T2[DEPTH][16];       // gates 10-13 products per 4-bit parity
    int    fixTab[NPASSES][16]; // low-nibble bank fixup
    int    fixShift[NPASSES];
    int    ffin;
};
__device__ Consts dC;

// ---------------- setup kernel (512 threads, 1 block) ----------------
__global__ void qnn_setup(const float* __restrict__ params)
{
    __shared__ int vg[NGATES], fg[NGATES];
    const int tid = threadIdx.x;

    if (tid == 0) {
        int v[NQ], f[NQ];
        #pragma unroll
        for (int q = 0; q < NQ; ++q) { v[q] = 1 << (NQ - 1 - q); f[q] = v[q]; }
        for (int l = 0; l < DEPTH; ++l) {
            for (int q = 0; q < NQ; ++q) { fg[l * NQ + q] = f[q]; vg[l * NQ + q] = v[q]; }
            for (int c = 0; c < NQ; ++c) {          // CX ring after the layer
                int t = (c + 1) % NQ;
                v[c] ^= v[t];
                f[t] ^= f[c];
            }
        }
        dC.ffin = f[0];
    }
    __syncthreads();

    if (tid < NGATES) {                              // per-gate constants
        int l = tid / NQ, q = tid % NQ;
        int grp  = (q < 5) ? 0 : (q < 10) ? 1 : 2;
        int base = (grp == 0) ? 0 : (grp == 1) ? 5 : 10;
        int p = l * 3 + grp, i = q - base;
        float tz = params[2 * tid];
        float ty = params[2 * tid + 1];
        dC.tq[p][i] = tanf(0.25f * ty);
        dC.sy[p][i] = sinf(0.5f * ty);
        float sH, cH, sF, cF;
        sincosf(0.5f * tz, &sH, &cH);
        sincosf(tz, &sF, &cF);
        dC.czH[p][i] = cH; dC.szH[p][i] = sH;
        dC.czF[p][i] = cF; dC.szF[p][i] = sF;
        dC.F[p][i]   = fg[tid];
        dC.M[p][i]   = vg[tid];
    }

    // T1: per-layer product of gates 5..9 half-angle factors, 32 sign combos
    if (tid < DEPTH * 32) {
        int l = tid >> 5, m = tid & 31;
        float zr = 1.0f, zi = 0.0f;
        for (int i = 0; i < 5; ++i) {
            float tz = params[2 * (l * NQ + 5 + i)];
            float s, c; sincosf(0.5f * tz, &s, &c);
            float sn = ((m >> i) & 1) ? s : -s;
            float t = zr * c - zi * sn;
            zi = zi * c + zr * sn;
            zr = t;
        }
        dC.T1[l][m] = make_float2(zr, zi);
    }
    // T2: gates 10..13, 16 combos
    if (tid >= 256 && tid < 256 + DEPTH * 16) {
        int idx = tid - 256;
        int l = idx >> 4, m = idx & 15;
        float zr = 1.0f, zi = 0.0f;
        for (int i = 0; i < 4; ++i) {
            float tz = params[2 * (l * NQ + 10 + i)];
            float s, c; sincosf(0.5f * tz, &s, &c);
            float sn = ((m >> i) & 1) ? s : -s;
            float t = zr * c - zi * sn;
            zi = zi * c + zr * sn;
            zr = t;
        }
        dC.T2[l][m] = make_float2(zr, zi);
    }

    if (tid < NPASSES) {                             // pass geometry
        int l = tid / 3, grp = tid % 3;
        int cnt  = (grp == 2) ? 4 : 5;
        int base = (grp == 0) ? 0 : (grp == 1) ? 5 : 10;
        int m[5] = {0, 0, 0, 0, 0};
        for (int i = 0; i < cnt; ++i) m[i] = vg[l * NQ + base + i];

        // GF(2) elimination; prefer pivot bits >= 4 (bank-friendly)
        int u[5], bp[5];
        for (int i = 0; i < cnt; ++i) {
            u[i] = m[i];
            for (int j = 0; j < i; ++j)
                if ((u[i] >> bp[j]) & 1) u[i] ^= u[j];
            int hi = u[i] & ~0xF;
            bp[i] = hi ? (31 - __clz(hi)) : (31 - __clz(u[i]));
            for (int j = 0; j < i; ++j)
                if ((u[j] >> bp[i]) & 1) u[j] ^= u[i];
        }
        for (int a = 0; a < cnt - 1; ++a)            // sort ascending
            for (int bq = 0; bq < cnt - 1 - a; ++bq)
                if (bp[bq] > bp[bq + 1]) { int t = bp[bq]; bp[bq] = bp[bq + 1]; bp[bq + 1] = t; }
        for (int i = 0; i < 5; ++i) dC.piv[tid][i] = (i < cnt) ? bp[i] : 30;

        // low-nibble fixup: copy spare rep-bits into pivot positions < 4
        int lowPiv[4], k = 0;
        for (int i = 0; i < cnt; ++i)
            if (bp[i] < 4) lowPiv[k++] = bp[i];
        dC.fixShift[tid] = 4 - k;
        for (int v = 0; v < 16; ++v) {
            int fv = 0;
            for (int i = 0; i < k; ++i)
                if ((v >> i) & 1) fv |= 1 << lowPiv[i];
            dC.fixTab[tid][v] = fv;
        }
    }
}

// ---------------- helpers ----------------
__device__ __forceinline__ u64 fma2(u64 a, u64 b, u64 c) {
    u64 d; asm("fma.rn.f32x2 %0, %1, %2, %3;" : "=l"(d) : "l"(a), "l"(b), "l"(c));
    return d;
}
__device__ __forceinline__ u64 pk(float lo, float hi) {
    u64 d; asm("mov.b64 %0, {%1, %2};" : "=l"(d) : "f"(lo), "f"(hi));
    return d;
}
__device__ __forceinline__ void upk(u64 v, float& lo, float& hi) {
    asm("mov.b64 {%0, %1}, %2;" : "=f"(lo), "=f"(hi) : "l"(v));
}
__device__ __forceinline__ u64 splat_sgn(float v, u32 sb) {
    u32 b = __float_as_uint(v) ^ sb;
    return ((u64)b << 32) | (u64)b;
}
__device__ __forceinline__ float fsgn(float v, u32 sb) {
    return __int_as_float(__float_as_int(v) ^ sb);
}

// insert zero bits at 5 sorted pivot positions (pad pivot 30 = no-op)
__device__ __forceinline__ int expand5(int p, const int* bp)
{
    #pragma unroll
    for (int i = 0; i < 5; ++i) {
        int m = (1 << bp[i]) - 1;
        p = ((p & ~m) << 1) | (p & m);
    }
    return p;
}

// compile-time lowest set bit index (for unrolled Off tree)
__device__ __forceinline__ constexpr int ctz4(int t) {
    return (t & 1) ? 0 : (t & 2) ? 1 : (t & 4) ? 2 : 3;
}

// ---------------- one pass ----------------
// MODE 0: layer diagonal + 5 shears (pass 1)
// MODE 1: 5 shears                  (pass 2)
// MODE 2: spare-partner dual block, 4 shears (pass 3)
// MODE 3: like 2, but accumulate sign*|amp|^2 instead of store (last pass)
template<int MODE>
__device__ __forceinline__ float do_pass(u64* __restrict__ sAmp, const Consts& sC,
                                         int p, int l, int tid)
{
    constexpr bool PHASE = (MODE == 0);
    constexpr bool G4    = (MODE <= 1);
    constexpr bool FINAL = (MODE == 3);
    const float2* sF2 = (const float2*)sAmp;

    int mk[4];
    #pragma unroll
    for (int i = 0; i < 4; ++i) mk[i] = sC.M[p][i];

    int jb = expand5(tid, sC.piv[p]);
    jb ^= sC.fixTab[p][(tid >> sC.fixShift[p]) & 15];

    const int m4 = G4 ? sC.M[p][4] : expand5(NTHREADS, sC.piv[p]);

    // parallel coset offsets: Off[g] = XOR of mk[i] over bits of g
    int Off[16];
    Off[0] = 0;
    #pragma unroll
    for (int t = 1; t < 16; ++t) Off[t] = Off[t & (t - 1)] ^ mk[ctz4(t)];

    int bb = 0;
    #pragma unroll
    for (int g = 0; g < 4; ++g)
        bb |= (__popc(sC.F[p][g] & jb) & 1) << g;
    if (G4) bb |= (__popc(sC.F[p][4] & jb) & 1) << 4;

    // upper-half role flips for spare-partner passes
    int wflip = 0;
    if (!G4) {
        #pragma unroll
        for (int g = 0; g < 4; ++g)
            wflip |= (__popc(sC.F[p][g] & m4) & 1) << g;
    }

    // ---- batched, fully independent loads ----
    u64 A[32];
    #pragma unroll
    for (int g = 0; g < 16; ++g) {
        A[g]      = sAmp[jb ^ Off[g]];
        A[g | 16] = sAmp[jb ^ Off[g] ^ m4];
    }

    // ---- phase stage (registers only, Gray order z-chain) ----
    if (PHASE) {
        int bb1 = 0, bb2 = 0;
        #pragma unroll
        for (int g = 0; g < 5; ++g)
            bb1 |= (__popc(sC.F[p + 1][g] & jb) & 1) << g;
        #pragma unroll
        for (int g = 0; g < 4; ++g)
            bb2 |= (__popc(sC.F[p + 2][g] & jb) & 1) << g;

        float zr = sC.czH[p][0];
        float zi = -fsgn(sC.szH[p][0], (u32)(bb & 1) << 31);
        #pragma unroll
        for (int k = 1; k < 5; ++k) {
            float c  = sC.czH[p][k];
            float sn = -fsgn(sC.szH[p][k], (u32)((bb >> k) & 1) << 31);
            float t  = zr * c - zi * sn;
            zi = zi * c + zr * sn;
            zr = t;
        }
        {
            float2 t1 = sC.T1[l][bb1];
            float t  = zr * t1.x - zi * t1.y;
            zi = zi * t1.x + zr * t1.y;
            zr = t;
            float2 t2 = sC.T2[l][bb2];
            t  = zr * t2.x - zi * t2.y;
            zi = zi * t2.x + zr * t2.y;
            zr = t;
        }
        const float cF0 = sC.czF[p][0], sF0  = fsgn(sC.szF[p][0], (u32)(bb & 1) << 31);
        const float cF1 = sC.czF[p][1], sF1  = fsgn(sC.szF[p][1], (u32)((bb >> 1) & 1) << 31);
        const float cF2 = sC.czF[p][2], sF2v = fsgn(sC.szF[p][2], (u32)((bb >> 2) & 1) << 31);
        const float cF3 = sC.czF[p][3], sF3  = fsgn(sC.szF[p][3], (u32)((bb >> 3) & 1) << 31);
        const float cF4 = sC.czF[p][4], sF4  = fsgn(sC.szF[p][4], (u32)((bb >> 4) & 1) << 31);
        float zbr = zr * cF4 - zi * sF4;
        float zbi = zi * cF4 + zr * sF4;

        #pragma unroll
        for (int u = 0; u < 16; ++u) {
            const int g = u ^ (u >> 1);
            float re, im;
            upk(A[g], re, im);
            A[g] = pk(re * zr - im * zi, im * zr + re * zi);
            upk(A[g | 16], re, im);
            A[g | 16] = pk(re * zbr - im * zbi, im * zbr + re * zbi);
            if (u < 15) {
                const int un = u + 1;
                const int c  = (un & 1) ? 0 : ((un & 2) ? 1 : ((un & 4) ? 2 : 3));
                const int gn = ((un ^ (un >> 1)) >> c) & 1;
                float cc = (c == 0) ? cF0 : (c == 1) ? cF1 : (c == 2) ? cF2 : cF3;
                float ss = (c == 0) ? sF0 : (c == 1) ? sF1 : (c == 2) ? sF2v : sF3;
                if (!gn) ss = -ss;
                float t = zr * cc - zi * ss;
                zi = zi * cc + zr * ss;
                zr = t;
                t   = zbr * cc - zbi * ss;
                zbi = zbi * cc + zbr * ss;
                zbr = t;
            }
        }
    }

    // ---- shear gates ----
    // gates 0..3 over within-half pairs (per-half signs for spare-partner)
    #pragma unroll
    for (int i = 0; i < 4; ++i) {
        const u32 sgA  = ((u32)((bb >> i) & 1)) << 31;
        const u64 tnvA = splat_sgn(sC.tq[p][i], sgA ^ 0x80000000u);
        const u64 svA  = splat_sgn(sC.sy[p][i], sgA);
        u64 tnvB = tnvA, svB = svA;
        if (!G4) {
            const u32 sgB = ((u32)(((bb ^ wflip) >> i) & 1)) << 31;
            tnvB = splat_sgn(sC.tq[p][i], sgB ^ 0x80000000u);
            svB  = splat_sgn(sC.sy[p][i], sgB);
        }
        #pragma unroll
        for (int t = 0; t < 32; ++t) {
            if (t & (1 << i)) continue;
            const int t1 = t | (1 << i);
            const u64 tnv = (t < 16) ? tnvA : tnvB;
            const u64 sv  = (t < 16) ? svA  : svB;
            u64 Av = A[t], Bv = A[t1];
            Av = fma2(Bv, tnv, Av);
            Bv = fma2(Av, sv,  Bv);
            Av = fma2(Bv, tnv, Av);
            A[t] = Av; A[t1] = Bv;
        }
    }
    // gate 4 over cross-half pairs (G4 modes only; W=I => same role per half pair)
    if (G4) {
        const u32 sg4  = ((u32)((bb >> 4) & 1)) << 31;
        const u64 tnv4 = splat_sgn(sC.tq[p][4], sg4 ^ 0x80000000u);
        const u64 sv4  = splat_sgn(sC.sy[p][4], sg4);
        #pragma unroll
        for (int t = 0; t < 16; ++t) {
            const int t1 = t | 16;
            u64 Av = A[t], Bv = A[t1];
            Av = fma2(Bv, tnv4, Av);
            Bv = fma2(Av, sv4,  Bv);
            Av = fma2(Bv, tnv4, Av);
            A[t] = Av; A[t1] = Bv;
        }
    }

    // ---- store (independent) or fused final accumulation ----
    float acc = 0.0f;
    if (FINAL) {
        const int ff  = sC.ffin;
        const u32 pb0 = (u32)(__popc(ff & jb) & 1) << 31;
        const u32 pb4 = (u32)(__popc(ff & m4) & 1) << 31;
        #pragma unroll
        for (int g = 0; g < 16; ++g) {
            const u32 sb  = pb0 ^ ((u32)(__popc(ff & Off[g]) & 1) << 31);
            float re, im;
            upk(A[g], re, im);
            acc = fmaf(fsgn(re, sb), re, acc);
            acc = fmaf(fsgn(im, sb), im, acc);
            upk(A[g | 16], re, im);
            const u32 sb2 = sb ^ pb4;
            acc = fmaf(fsgn(re, sb2), re, acc);
            acc = fmaf(fsgn(im, sb2), im, acc);
        }
    } else {
        #pragma unroll
        for (int g = 0; g < 16; ++g) {
            sAmp[jb ^ Off[g]]      = A[g];
            sAmp[jb ^ Off[g] ^ m4] = A[g | 16];
        }
    }
    (void)sF2;
    return acc;
}

// ---------------- main kernel ----------------
__global__ __launch_bounds__(NTHREADS, 1)
void qnn_kernel(const float* __restrict__ x, float* __restrict__ out)
{
    extern __shared__ u64 sAmp[];                  // [QDIM] packed (re,im)

    __shared__ Consts sC;
    __shared__ float cq[NQ], sq[NQ];
    __shared__ float tabLo[128], tabHi[128];
    __shared__ float redbuf[NTHREADS / 32];

    const int tid = threadIdx.x;
    const int b   = blockIdx.x;

    {   // copy constants to smem
        const int n = (int)(sizeof(Consts) / 4);
        const int* src = (const int*)&dC;
        int* dst = (int*)&sC;
        for (int i = tid; i < n; i += NTHREADS) dst[i] = src[i];
    }

    if (tid < NQ) {
        float ang = x[b * NQ + tid] * 1.57079632679489662f;
        float s, c;
        sincosf(ang, &s, &c);
        cq[tid] = c;
        sq[tid] = s;
    }
    __syncthreads();

    // product-state tables (initial RY layer on |0...0>)
    if (tid < 128) {
        float p = 1.0f;
        #pragma unroll
        for (int k = 0; k < 7; ++k)
            p *= ((tid >> k) & 1) ? sq[NQ - 1 - k] : cq[NQ - 1 - k];
        tabLo[tid] = p;
    } else if (tid < 256) {
        int m = tid - 128;
        float p = 1.0f;
        #pragma unroll
        for (int k = 0; k < 7; ++k)
            p *= ((m >> k) & 1) ? sq[6 - k] : cq[6 - k];
        tabHi[m] = p;
    }
    __syncthreads();

    #pragma unroll
    for (int k = 0; k < QDIM / NTHREADS; ++k) {
        int j = tid + k * NTHREADS;
        sAmp[j] = (u64)__float_as_uint(tabHi[j >> 7] * tabLo[j & 127]);
    }

    // ---- 24 passes: per layer [D+5RY], [5RY], [4RY]; last pass accumulates ----
    float accOut = 0.0f;
    #pragma unroll 1
    for (int l = 0; l < DEPTH; ++l) {
        const int p = 3 * l;
        __syncthreads();
        do_pass<0>(sAmp, sC, p, l, tid);
        __syncthreads();
        do_pass<1>(sAmp, sC, p + 1, l, tid);
        __syncthreads();
        if (l != DEPTH - 1) {
            do_pass<2>(sAmp, sC, p + 2, l, tid);
        } else {
            accOut = do_pass<3>(sAmp, sC, p + 2, l, tid);
        }
    }

    // ---- reduction of per-thread expectation contributions ----
    float acc = accOut;
    #pragma unroll
    for (int off = 16; off > 0; off >>= 1)
        acc += __shfl_down_sync(0xffffffffu, acc, off);
    if ((tid & 31) == 0) redbuf[tid >> 5] = acc;
    __syncthreads();
    if (tid < 32) {
        float t = (tid < NTHREADS / 32) ? redbuf[tid] : 0.0f;
        #pragma unroll
        for (int off = 8; off > 0; off >>= 1)
            t += __shfl_down_sync(0xffffffffu, t, off);
        if (tid == 0) out[b] = (t + 1.0f) * 0.5f;
    }
}

extern "C" void kernel_launch(void* const* d_in, const int* in_sizes, int n_in,
                              void* d_out, int out_size)
{
    const float* x      = (const float*)d_in[0];   // (2048, 14)
    const float* params = (const float*)d_in[1];   // (224,)
    float* out          = (float*)d_out;           // (2048,)
    (void)in_sizes; (void)n_in;

    qnn_setup<<<1, 512>>>(params);

    const size_t shmem = (size_t)QDIM * sizeof(u64);   // 128 KB
    cudaFuncSetAttribute(qnn_kernel,
                         cudaFuncAttributeMaxDynamicSharedMemorySize,
                         (int)shmem);
    qnn_kernel<<<out_size, NTHREADS, shmem>>>(x, out);
}

// round 15
// speedup vs baseline: 1.0425x; 1.0425x over previous
#include <cuda_runtime.h>

// QNNClassifier: 14-qubit statevector, BATCH=2048, DEPTH=8.
// One CTA/batch element; state = QDIM packed (re,im) u64 in smem (128 KB).
// CX deferred as GF(2) relabeling; per layer gates grouped 5+5+4 (same sigma
// frame => W=I; whole-layer diagonal applied once in pass 1; passes 2/3 pure
// real-shear). R10-proven structure (Gray-chain addressing, dual z-chains,
// 3-shear packed-f32x2 butterflies) plus: per-pass setup hoisted above the
// barrier, explicit layer loop (no divides), and the final |amp|^2 reduction
// fused into layer-8 pass-3 (no final store or readback sweeps).
// (Resubmission of R13 source: previous bench died in the broker, not on GPU.)

#define NQ       14
#define QDIM     16384
#define DEPTH    8
#define NGATES   (DEPTH * NQ)   // 112
#define NPASSES  (DEPTH * 3)    // 24
#define NTHREADS 512

typedef unsigned long long u64;
typedef unsigned int u32;

struct __align__(16) Consts {
    int    piv[NPASSES][5];     // sorted pivot bits (pad 30)
    int    M[NPASSES][5];       // flip masks per gate
    int    F[NPASSES][5];       // parity masks per gate
    float  tq[NPASSES][5];      // tan(ty/4)
    float  sy[NPASSES][5];      // sin(ty/2)
    float  czH[NPASSES][5];     // cos(tz/2)
    float  szH[NPASSES][5];     // sin(tz/2)
    float  czF[NPASSES][5];     // cos(tz)
    float  szF[NPASSES][5];     // sin(tz)
    float2 T1[DEPTH][32];       // gates 5-9 half-angle products per 5-bit parity
    float2 T2[DEPTH][16];       // gates 10-13 products per 4-bit parity
    int    fixTab[NPASSES][16]; // low-nibble bank fixup
    int    fixShift[NPASSES];
    int    ffin;
};
__device__ Consts dC;

// ---------------- setup kernel (512 threads, 1 block) ----------------
__global__ void qnn_setup(const float* __restrict__ params)
{
    __shared__ int vg[NGATES], fg[NGATES];
    const int tid = threadIdx.x;

    if (tid == 0) {
        int v[NQ], f[NQ];
        #pragma unroll
        for (int q = 0; q < NQ; ++q) { v[q] = 1 << (NQ - 1 - q); f[q] = v[q]; }
        for (int l = 0; l < DEPTH; ++l) {
            for (int q = 0; q < NQ; ++q) { fg[l * NQ + q] = f[q]; vg[l * NQ + q] = v[q]; }
            for (int c = 0; c < NQ; ++c) {          // CX ring after the layer
                int t = (c + 1) % NQ;
                v[c] ^= v[t];
                f[t] ^= f[c];
            }
        }
        dC.ffin = f[0];
    }
    __syncthreads();

    if (tid < NGATES) {                              // per-gate constants
        int l = tid / NQ, q = tid % NQ;
        int grp  = (q < 5) ? 0 : (q < 10) ? 1 : 2;
        int base = (grp == 0) ? 0 : (grp == 1) ? 5 : 10;
        int p = l * 3 + grp, i = q - base;
        float tz = params[2 * tid];
        float ty = params[2 * tid + 1];
        dC.tq[p][i] = tanf(0.25f * ty);
        dC.sy[p][i] = sinf(0.5f * ty);
        float sH, cH, sF, cF;
        sincosf(0.5f * tz, &sH, &cH);
        sincosf(tz, &sF, &cF);
        dC.czH[p][i] = cH; dC.szH[p][i] = sH;
        dC.czF[p][i] = cF; dC.szF[p][i] = sF;
        dC.F[p][i]   = fg[tid];
        dC.M[p][i]   = vg[tid];
    }

    // T1: per-layer product of gates 5..9 half-angle factors, 32 sign combos
    if (tid < DEPTH * 32) {
        int l = tid >> 5, m = tid & 31;
        float zr = 1.0f, zi = 0.0f;
        for (int i = 0; i < 5; ++i) {
            float tz = params[2 * (l * NQ + 5 + i)];
            float s, c; sincosf(0.5f * tz, &s, &c);
            float sn = ((m >> i) & 1) ? s : -s;
            float t = zr * c - zi * sn;
            zi = zi * c + zr * sn;
            zr = t;
        }
        dC.T1[l][m] = make_float2(zr, zi);
    }
    // T2: gates 10..13, 16 combos
    if (tid >= 256 && tid < 256 + DEPTH * 16) {
        int idx = tid - 256;
        int l = idx >> 4, m = idx & 15;
        float zr = 1.0f, zi = 0.0f;
        for (int i = 0; i < 4; ++i) {
            float tz = params[2 * (l * NQ + 10 + i)];
            float s, c; sincosf(0.5f * tz, &s, &c);
            float sn = ((m >> i) & 1) ? s : -s;
            float t = zr * c - zi * sn;
            zi = zi * c + zr * sn;
            zr = t;
        }
        dC.T2[l][m] = make_float2(zr, zi);
    }

    if (tid < NPASSES) {                             // pass geometry
        int l = tid / 3, grp = tid % 3;
        int cnt  = (grp == 2) ? 4 : 5;
        int base = (grp == 0) ? 0 : (grp == 1) ? 5 : 10;
        int m[5] = {0, 0, 0, 0, 0};
        for (int i = 0; i < cnt; ++i) m[i] = vg[l * NQ + base + i];

        // GF(2) elimination; prefer pivot bits >= 4 (bank-friendly)
        int u[5], bp[5];
        for (int i = 0; i < cnt; ++i) {
            u[i] = m[i];
            for (int j = 0; j < i; ++j)
                if ((u[i] >> bp[j]) & 1) u[i] ^= u[j];
            int hi = u[i] & ~0xF;
            bp[i] = hi ? (31 - __clz(hi)) : (31 - __clz(u[i]));
            for (int j = 0; j < i; ++j)
                if ((u[j] >> bp[i]) & 1) u[j] ^= u[i];
        }
        for (int a = 0; a < cnt - 1; ++a)            // sort ascending
            for (int bq = 0; bq < cnt - 1 - a; ++bq)
                if (bp[bq] > bp[bq + 1]) { int t = bp[bq]; bp[bq] = bp[bq + 1]; bp[bq + 1] = t; }
        for (int i = 0; i < 5; ++i) dC.piv[tid][i] = (i < cnt) ? bp[i] : 30;

        // low-nibble fixup: copy spare rep-bits into pivot positions < 4
        int lowPiv[4], k = 0;
        for (int i = 0; i < cnt; ++i)
            if (bp[i] < 4) lowPiv[k++] = bp[i];
        dC.fixShift[tid] = 4 - k;
        for (int v = 0; v < 16; ++v) {
            int fv = 0;
            for (int i = 0; i < k; ++i)
                if ((v >> i) & 1) fv |= 1 << lowPiv[i];
            dC.fixTab[tid][v] = fv;
        }
    }
}

// ---------------- helpers ----------------
__device__ __forceinline__ u64 fma2(u64 a, u64 b, u64 c) {
    u64 d; asm("fma.rn.f32x2 %0, %1, %2, %3;" : "=l"(d) : "l"(a), "l"(b), "l"(c));
    return d;
}
__device__ __forceinline__ u64 pk(float lo, float hi) {
    u64 d; asm("mov.b64 %0, {%1, %2};" : "=l"(d) : "f"(lo), "f"(hi));
    return d;
}
__device__ __forceinline__ void upk(u64 v, float& lo, float& hi) {
    asm("mov.b64 {%0, %1}, %2;" : "=f"(lo), "=f"(hi) : "l"(v));
}
__device__ __forceinline__ u64 splat_sgn(float v, u32 sb) {
    u32 b = __float_as_uint(v) ^ sb;
    return ((u64)b << 32) | (u64)b;
}
__device__ __forceinline__ float fsgn(float v, u32 sb) {
    return __int_as_float(__float_as_int(v) ^ sb);
}

// insert zero bits at 5 sorted pivot positions (pad pivot 30 = no-op)
__device__ __forceinline__ int expand5(int p, const int* bp)
{
    #pragma unroll
    for (int i = 0; i < 5; ++i) {
        int m = (1 << bp[i]) - 1;
        p = ((p & ~m) << 1) | (p & m);
    }
    return p;
}

// ---------------- pass bodies (setup-before-barrier inside) ----------------

// pass 1: whole-layer diagonal + 5 shears, one 32-amp coset per thread
__device__ __forceinline__ void pass_phase(u64* __restrict__ sAmp, const Consts& sC,
                                           int p, int l, int tid)
{
    const float2* sF2 = (const float2*)sAmp;
    int mk[5];
    #pragma unroll
    for (int i = 0; i < 5; ++i) mk[i] = sC.M[p][i];

    int jb = expand5(tid, sC.piv[p]);
    jb ^= sC.fixTab[p][(tid >> sC.fixShift[p]) & 15];

    int bb = 0, bb1 = 0, bb2 = 0;
    #pragma unroll
    for (int g = 0; g < 5; ++g)
        bb |= (__popc(sC.F[p][g] & jb) & 1) << g;
    #pragma unroll
    for (int g = 0; g < 5; ++g)
        bb1 |= (__popc(sC.F[p + 1][g] & jb) & 1) << g;
    #pragma unroll
    for (int g = 0; g < 4; ++g)
        bb2 |= (__popc(sC.F[p + 2][g] & jb) & 1) << g;

    // z0 = (own 5 half-angle factors, role-signed) * T1[bb1] * T2[bb2]
    float zr = sC.czH[p][0];
    float zi = -fsgn(sC.szH[p][0], (u32)(bb & 1) << 31);
    #pragma unroll
    for (int k = 1; k < 5; ++k) {
        float c  = sC.czH[p][k];
        float sn = -fsgn(sC.szH[p][k], (u32)((bb >> k) & 1) << 31);
        float t  = zr * c - zi * sn;
        zi = zi * c + zr * sn;
        zr = t;
    }
    {
        float2 t1 = sC.T1[l][bb1];
        float t  = zr * t1.x - zi * t1.y;
        zi = zi * t1.x + zr * t1.y;
        zr = t;
        float2 t2 = sC.T2[l][bb2];
        t  = zr * t2.x - zi * t2.y;
        zi = zi * t2.x + zr * t2.y;
        zr = t;
    }
    const float cF0 = sC.czF[p][0], sF0  = fsgn(sC.szF[p][0], (u32)(bb & 1) << 31);
    const float cF1 = sC.czF[p][1], sF1  = fsgn(sC.szF[p][1], (u32)((bb >> 1) & 1) << 31);
    const float cF2 = sC.czF[p][2], sF2v = fsgn(sC.szF[p][2], (u32)((bb >> 2) & 1) << 31);
    const float cF3 = sC.czF[p][3], sF3  = fsgn(sC.szF[p][3], (u32)((bb >> 3) & 1) << 31);
    const float cF4 = sC.czF[p][4], sF4  = fsgn(sC.szF[p][4], (u32)((bb >> 4) & 1) << 31);
    float zbr = zr * cF4 - zi * sF4;
    float zbi = zi * cF4 + zr * sF4;

    __syncthreads();                                // barrier AFTER setup

    // dual 4-bit Gray walk: slot g (bit4=0) with zA, slot g|16 with zB
    u64 A[32];
    {
        int j = jb;
        const int m4 = mk[4];
        #pragma unroll
        for (int u = 0; u < 16; ++u) {
            const int g = u ^ (u >> 1);
            float2 a  = sF2[j];
            float2 c2 = sF2[j ^ m4];
            A[g]      = pk(a.x * zr - a.y * zi,     a.y * zr + a.x * zi);
            A[g | 16] = pk(c2.x * zbr - c2.y * zbi, c2.y * zbr + c2.x * zbi);
            if (u < 15) {
                const int un = u + 1;
                const int c  = (un & 1) ? 0 : ((un & 2) ? 1 : ((un & 4) ? 2 : 3));
                const int gn = ((un ^ (un >> 1)) >> c) & 1;
                float cc = (c == 0) ? cF0 : (c == 1) ? cF1 : (c == 2) ? cF2 : cF3;
                float ss = (c == 0) ? sF0 : (c == 1) ? sF1 : (c == 2) ? sF2v : sF3;
                if (!gn) ss = -ss;
                float t = zr * cc - zi * ss;
                zi = zi * cc + zr * ss;
                zr = t;
                t   = zbr * cc - zbi * ss;
                zbi = zbi * cc + zbr * ss;
                zbr = t;
                j ^= mk[c];
            }
        }
    }

    // 5 RY gates as 3-shear butterflies
    #pragma unroll
    for (int i = 0; i < 5; ++i) {
        const u32 sg  = ((u32)((bb >> i) & 1)) << 31;
        const u64 tnv = splat_sgn(sC.tq[p][i], sg ^ 0x80000000u);
        const u64 sv  = splat_sgn(sC.sy[p][i], sg);
        #pragma unroll
        for (int t = 0; t < 32; ++t) {
            if (t & (1 << i)) continue;
            const int t1 = t | (1 << i);
            u64 Av = A[t], Bv = A[t1];
            Av = fma2(Bv, tnv, Av);
            Bv = fma2(Av, sv,  Bv);
            Av = fma2(Bv, tnv, Av);
            A[t] = Av; A[t1] = Bv;
        }
    }

    // dual Gray store
    {
        int j = jb;
        const int m4 = mk[4];
        #pragma unroll
        for (int u = 0; u < 16; ++u) {
            const int g = u ^ (u >> 1);
            sAmp[j]      = A[g];
            sAmp[j ^ m4] = A[g | 16];
            if (u < 15) {
                const int un = u + 1;
                const int c  = (un & 1) ? 0 : ((un & 2) ? 1 : ((un & 4) ? 2 : 3));
                j ^= mk[c];
            }
        }
    }
}

// pass 2: pure shear, 5 gates, one 32-amp coset per thread
__device__ __forceinline__ void pass_shear5(u64* __restrict__ sAmp, const Consts& sC,
                                            int p, int tid)
{
    int mk[5];
    #pragma unroll
    for (int i = 0; i < 5; ++i) mk[i] = sC.M[p][i];

    int jb = expand5(tid, sC.piv[p]);
    jb ^= sC.fixTab[p][(tid >> sC.fixShift[p]) & 15];

    int bb = 0;
    #pragma unroll
    for (int g = 0; g < 5; ++g)
        bb |= (__popc(sC.F[p][g] & jb) & 1) << g;

    __syncthreads();                                // barrier AFTER setup

    u64 A[32];
    {
        int j = jb;
        const int m4 = mk[4];
        #pragma unroll
        for (int u = 0; u < 16; ++u) {
            const int g = u ^ (u >> 1);
            A[g]      = sAmp[j];
            A[g | 16] = sAmp[j ^ m4];
            if (u < 15) {
                const int un = u + 1;
                const int c  = (un & 1) ? 0 : ((un & 2) ? 1 : ((un & 4) ? 2 : 3));
                j ^= mk[c];
            }
        }
    }

    #pragma unroll
    for (int i = 0; i < 5; ++i) {
        const u32 sg  = ((u32)((bb >> i) & 1)) << 31;
        const u64 tnv = splat_sgn(sC.tq[p][i], sg ^ 0x80000000u);
        const u64 sv  = splat_sgn(sC.sy[p][i], sg);
        #pragma unroll
        for (int t = 0; t < 32; ++t) {
            if (t & (1 << i)) continue;
            const int t1 = t | (1 << i);
            u64 Av = A[t], Bv = A[t1];
            Av = fma2(Bv, tnv, Av);
            Bv = fma2(Av, sv,  Bv);
            Av = fma2(Bv, tnv, Av);
            A[t] = Av; A[t1] = Bv;
        }
    }

    {
        int j = jb;
        const int m4 = mk[4];
        #pragma unroll
        for (int u = 0; u < 16; ++u) {
            const int g = u ^ (u >> 1);
            sAmp[j]      = A[g];
            sAmp[j ^ m4] = A[g | 16];
            if (u < 15) {
                const int un = u + 1;
                const int c  = (un & 1) ? 0 : ((un & 2) ? 1 : ((un & 4) ? 2 : 3));
                j ^= mk[c];
            }
        }
    }
}

// pass 3: pure shear, 4 gates, two 16-amp cosets; FINAL accumulates |amp|^2
template<bool FINAL>
__device__ __forceinline__ float pass_shear4(u64* __restrict__ sAmp, const Consts& sC,
                                             int p, int tid)
{
    int mk[4];
    #pragma unroll
    for (int i = 0; i < 4; ++i) mk[i] = sC.M[p][i];
    const int fsh = sC.fixShift[p];

    // setup for both cosets before the barrier
    int jbs[2], bbs[2];
    #pragma unroll
    for (int kk = 0; kk < 2; ++kk) {
        const int pp = tid + kk * NTHREADS;
        int jb = expand5(pp, sC.piv[p]);
        jb ^= sC.fixTab[p][(pp >> fsh) & 15];
        int bb = 0;
        #pragma unroll
        for (int g = 0; g < 4; ++g)
            bb |= (__popc(sC.F[p][g] & jb) & 1) << g;
        jbs[kk] = jb; bbs[kk] = bb;
    }

    __syncthreads();                                // barrier AFTER setup

    float acc = 0.0f;
    const int ff = sC.ffin;

    #pragma unroll
    for (int kk = 0; kk < 2; ++kk) {
        const int jb = jbs[kk];
        const int bb = bbs[kk];

        u64 A[16];
        {
            int j = jb;
            #pragma unroll
            for (int u = 0; u < 16; ++u) {
                const int g = u ^ (u >> 1);
                A[g] = sAmp[j];
                if (u < 15) {
                    const int un = u + 1;
                    const int c  = (un & 1) ? 0 : ((un & 2) ? 1 : ((un & 4) ? 2 : 3));
                    j ^= mk[c];
                }
            }
        }

        #pragma unroll
        for (int i = 0; i < 4; ++i) {
            const u32 sg  = ((u32)((bb >> i) & 1)) << 31;
            const u64 tnv = splat_sgn(sC.tq[p][i], sg ^ 0x80000000u);
            const u64 sv  = splat_sgn(sC.sy[p][i], sg);
            #pragma unroll
            for (int t = 0; t < 16; ++t) {
                if (t & (1 << i)) continue;
                const int t1 = t | (1 << i);
                u64 Av = A[t], Bv = A[t1];
                Av = fma2(Bv, tnv, Av);
                Bv = fma2(Av, sv,  Bv);
                Av = fma2(Bv, tnv, Av);
                A[t] = Av; A[t1] = Bv;
            }
        }

        {
            int j = jb;
            #pragma unroll
            for (int u = 0; u < 16; ++u) {
                const int g = u ^ (u >> 1);
                if (FINAL) {
                    float re, im;
                    upk(A[g], re, im);
                    const u32 sb = (u32)(__popc(ff & j) & 1) << 31;
                    acc = fmaf(fsgn(re, sb), re, acc);
                    acc = fmaf(fsgn(im, sb), im, acc);
                } else {
                    sAmp[j] = A[g];
                }
                if (u < 15) {
                    const int un = u + 1;
                    const int c  = (un & 1) ? 0 : ((un & 2) ? 1 : ((un & 4) ? 2 : 3));
                    j ^= mk[c];
                }
            }
        }
    }
    return acc;
}

// ---------------- main kernel ----------------
__global__ __launch_bounds__(NTHREADS, 1)
void qnn_kernel(const float* __restrict__ x, float* __restrict__ out)
{
    extern __shared__ u64 sAmp[];                  // [QDIM] packed (re,im)

    __shared__ Consts sC;
    __shared__ float cq[NQ], sq[NQ];
    __shared__ float tabLo[128], tabHi[128];
    __shared__ float redbuf[NTHREADS / 32];

    const int tid = threadIdx.x;
    const int b   = blockIdx.x;

    {   // copy constants to smem
        const int n = (int)(sizeof(Consts) / 4);
        const int* src = (const int*)&dC;
        int* dst = (int*)&sC;
        for (int i = tid; i < n; i += NTHREADS) dst[i] = src[i];
    }

    if (tid < NQ) {
        float ang = x[b * NQ + tid] * 1.57079632679489662f;
        float s, c;
        sincosf(ang, &s, &c);
        cq[tid] = c;
        sq[tid] = s;
    }
    __syncthreads();

    // product-state tables (initial RY layer on |0...0>)
    if (tid < 128) {
        float p = 1.0f;
        #pragma unroll
        for (int k = 0; k < 7; ++k)
            p *= ((tid >> k) & 1) ? sq[NQ - 1 - k] : cq[NQ - 1 - k];
        tabLo[tid] = p;
    } else if (tid < 256) {
        int m = tid - 128;
        float p = 1.0f;
        #pragma unroll
        for (int k = 0; k < 7; ++k)
            p *= ((m >> k) & 1) ? sq[6 - k] : cq[6 - k];
        tabHi[m] = p;
    }
    __syncthreads();

    #pragma unroll
    for (int k = 0; k < QDIM / NTHREADS; ++k) {
        int j = tid + k * NTHREADS;
        sAmp[j] = (u64)__float_as_uint(tabHi[j >> 7] * tabLo[j & 127]);
    }

    // ---- 24 passes: per layer [D+5RY], [5RY], [4RY]; last pass accumulates ----
    float accOut = 0.0f;
    #pragma unroll 1
    for (int l = 0; l < DEPTH; ++l) {
        const int p = 3 * l;
        pass_phase(sAmp, sC, p, l, tid);
        pass_shear5(sAmp, sC, p + 1, tid);
        if (l != DEPTH - 1) {
            pass_shear4<false>(sAmp, sC, p + 2, tid);
        } else {
            accOut = pass_shear4<true>(sAmp, sC, p + 2, tid);
        }
    }

    // ---- reduction of per-thread expectation contributions ----
    float acc = accOut;
    #pragma unroll
    for (int off = 16; off > 0; off >>= 1)
        acc += __shfl_down_sync(0xffffffffu, acc, off);
    if ((tid & 31) == 0) redbuf[tid >> 5] = acc;
    __syncthreads();
    if (tid < 32) {
        float t = (tid < NTHREADS / 32) ? redbuf[tid] : 0.0f;
        #pragma unroll
        for (int off = 8; off > 0; off >>= 1)
            t += __shfl_down_sync(0xffffffffu, t, off);
        if (tid == 0) out[b] = (t + 1.0f) * 0.5f;
    }
}

extern "C" void kernel_launch(void* const* d_in, const int* in_sizes, int n_in,
                              void* d_out, int out_size)
{
    const float* x      = (const float*)d_in[0];   // (2048, 14)
    const float* params = (const float*)d_in[1];   // (224,)
    float* out          = (float*)d_out;           // (2048,)
    (void)in_sizes; (void)n_in;

    qnn_setup<<<1, 512>>>(params);

    const size_t shmem = (size_t)QDIM * sizeof(u64);   // 128 KB
    cudaFuncSetAttribute(qnn_kernel,
                         cudaFuncAttributeMaxDynamicSharedMemorySize,
                         (int)shmem);
    qnn_kernel<<<out_size, NTHREADS, shmem>>>(x, out);
}